// round 2
// baseline (speedup 1.0000x reference)
#include <cuda_runtime.h>

#define NN 100000
#define NE 1250000
#define D  64
#define NB 16

// Scratch (no allocs allowed). Invariant: g_h and g_deg are ZERO at entry of
// every kernel_launch call — they are zero at module load, and k_transform
// restores them to zero after consuming them. No memsets needed.
__device__ float g_h[(size_t)NN * D];   // sum of x[src] per dst node
__device__ float g_deg[NN];             // in-degree (float)
__device__ float g_Wm[D * D];           // reconstructed W_msg  [i][o]
__device__ float g_Ws[D * D];           // reconstructed W_self [i][o]
__device__ float g_bm[D];
__device__ float g_bs[D];

// ---------------------------------------------------------------------------
// Kernel 1: scatter-add raw x rows (16 threads/edge, float4 vector atomics).
// Block 0 instead reconstructs the weights from the bases — this work hides
// entirely under the scatter, removing a serial kernel launch.
// ---------------------------------------------------------------------------
__global__ void k_scatter(const float4* __restrict__ x4, const int* __restrict__ ei,
                          const float* __restrict__ bmw, const float* __restrict__ bmb,
                          const float* __restrict__ bsw, const float* __restrict__ bsb,
                          const float* __restrict__ lc) {
    if (blockIdx.x == 0) {
        __shared__ float c[NB];
        if (threadIdx.x < NB) c[threadIdx.x] = lc[threadIdx.x];
        __syncthreads();
        for (int idx = threadIdx.x; idx < D * D; idx += 256) {
            float wm = 0.f, ws = 0.f;
            #pragma unroll
            for (int b = 0; b < NB; b++) {
                wm = fmaf(bmw[idx * NB + b], c[b], wm);
                ws = fmaf(bsw[idx * NB + b], c[b], ws);
            }
            g_Wm[idx] = wm;
            g_Ws[idx] = ws;
        }
        if (threadIdx.x < D) {
            int o = threadIdx.x;
            float bm = 0.f, bs = 0.f;
            #pragma unroll
            for (int b = 0; b < NB; b++) {
                bm = fmaf(bmb[o * NB + b], c[b], bm);
                bs = fmaf(bsb[o * NB + b], c[b], bs);
            }
            g_bm[o] = bm;
            g_bs[o] = bs;
        }
        return;
    }
    unsigned t = (blockIdx.x - 1) * blockDim.x + threadIdx.x;
    unsigned e = t >> 4;
    if (e >= NE) return;
    int j = t & 15;
    int src = __ldg(ei + e);
    int dst = __ldg(ei + NE + e);
    float4 v = __ldg(x4 + (size_t)src * (D / 4) + j);
    float* p = g_h + (size_t)dst * D + j * 4;
    asm volatile("red.global.add.v4.f32 [%0], {%1,%2,%3,%4};"
                 :: "l"(p), "f"(v.x), "f"(v.y), "f"(v.z), "f"(v.w)
                 : "memory");
    if (j == 0) atomicAdd(&g_deg[dst], 1.0f);
}

// ---------------------------------------------------------------------------
// Kernel 2: out = normalize( h @ Wm + x @ Ws + deg*bm + bs )
// 64 nodes x 64 cols per block.  Inner loop uses packed fma.rn.f32x2 (2x the
// FFMA issue rate vs scalar FFMA on sm_100).  The A operand is stored
// DUPLICATED in shared ([v,v] pairs) so an LDS.64 yields the packed operand
// directly — no per-iteration pack movs.  Also restores g_h/g_deg to zero.
// ---------------------------------------------------------------------------
#define IN2_STRIDE 264   // 2*128 duplicated + 8 pad (keeps 16B alignment)

__global__ void k_transform(const float* __restrict__ x, float* __restrict__ out) {
    extern __shared__ float smem[];
    float* In2  = smem;                      // [64][IN2_STRIDE] duplicated pairs
    float* Wsh  = In2 + 64 * IN2_STRIDE;     // [128][64] flat (rows 0..63 Wm, 64..127 Ws)
    float* red  = Wsh + 128 * D;             // [64][17]
    float* nf   = red + 64 * 17;             // [64]
    float* degS = nf + 64;                   // [64]

    int tid = threadIdx.x;
    int n0  = blockIdx.x * 64;

    // Load W
    {
        const float4* wm4 = (const float4*)g_Wm;
        const float4* ws4 = (const float4*)g_Ws;
        float4* w4 = (float4*)Wsh;
        #pragma unroll
        for (int i = tid; i < (D * D) / 4; i += 256) {
            w4[i] = wm4[i];
            w4[i + (D * D) / 4] = ws4[i];
        }
    }
    // Load input tile duplicated: In2[n][2k]=In2[n][2k+1]=concat(h,x)[n][k].
    // Also restore g_h to zero for the next launch.
    {
        const float4* h4 = (const float4*)g_h;
        const float4* x4 = (const float4*)x;
        float4* h4w = (float4*)g_h;
        for (int i = tid; i < 64 * (D / 4); i += 256) {
            int n = i >> 4, j = i & 15;
            int gn = n0 + n;
            float4 hv = make_float4(0.f, 0.f, 0.f, 0.f);
            float4 xv = hv;
            if (gn < NN) {
                size_t off = (size_t)gn * (D / 4) + j;
                hv = h4[off];
                xv = x4[off];
                h4w[off] = make_float4(0.f, 0.f, 0.f, 0.f);
            }
            float2* ph = (float2*)&In2[n * IN2_STRIDE + 2 * (j * 4)];
            ph[0] = make_float2(hv.x, hv.x);
            ph[1] = make_float2(hv.y, hv.y);
            ph[2] = make_float2(hv.z, hv.z);
            ph[3] = make_float2(hv.w, hv.w);
            float2* px = (float2*)&In2[n * IN2_STRIDE + 2 * (64 + j * 4)];
            px[0] = make_float2(xv.x, xv.x);
            px[1] = make_float2(xv.y, xv.y);
            px[2] = make_float2(xv.z, xv.z);
            px[3] = make_float2(xv.w, xv.w);
        }
    }
    // Load degree (and restore to zero)
    if (tid < 64) {
        int gn = n0 + tid;
        float dg = 0.f;
        if (gn < NN) {
            dg = g_deg[gn];
            g_deg[gn] = 0.f;
        }
        degS[tid] = dg;
    }
    __syncthreads();

    int to = tid & 15;   // col group: cols to*4 .. to*4+3
    int tn = tid >> 4;   // node group: nodes tn*4 .. tn*4+3

    unsigned long long acc[4][2];
    #pragma unroll
    for (int r = 0; r < 4; r++) { acc[r][0] = 0ull; acc[r][1] = 0ull; }

    const float* a0 = &In2[(tn * 4 + 0) * IN2_STRIDE];
    const float* a1 = &In2[(tn * 4 + 1) * IN2_STRIDE];
    const float* a2 = &In2[(tn * 4 + 2) * IN2_STRIDE];
    const float* a3 = &In2[(tn * 4 + 3) * IN2_STRIDE];
    const float* wp = &Wsh[to * 4];

    #pragma unroll 8
    for (int k = 0; k < 128; k++) {
        float4 b = *(const float4*)(wp + k * D);
        unsigned long long b01, b23;
        asm("mov.b64 %0, {%1,%2};" : "=l"(b01) : "f"(b.x), "f"(b.y));
        asm("mov.b64 %0, {%1,%2};" : "=l"(b23) : "f"(b.z), "f"(b.w));
        unsigned long long v0 = *(const unsigned long long*)(a0 + 2 * k);
        unsigned long long v1 = *(const unsigned long long*)(a1 + 2 * k);
        unsigned long long v2 = *(const unsigned long long*)(a2 + 2 * k);
        unsigned long long v3 = *(const unsigned long long*)(a3 + 2 * k);
        asm("fma.rn.f32x2 %0, %1, %2, %0;" : "+l"(acc[0][0]) : "l"(v0), "l"(b01));
        asm("fma.rn.f32x2 %0, %1, %2, %0;" : "+l"(acc[0][1]) : "l"(v0), "l"(b23));
        asm("fma.rn.f32x2 %0, %1, %2, %0;" : "+l"(acc[1][0]) : "l"(v1), "l"(b01));
        asm("fma.rn.f32x2 %0, %1, %2, %0;" : "+l"(acc[1][1]) : "l"(v1), "l"(b23));
        asm("fma.rn.f32x2 %0, %1, %2, %0;" : "+l"(acc[2][0]) : "l"(v2), "l"(b01));
        asm("fma.rn.f32x2 %0, %1, %2, %0;" : "+l"(acc[2][1]) : "l"(v2), "l"(b23));
        asm("fma.rn.f32x2 %0, %1, %2, %0;" : "+l"(acc[3][0]) : "l"(v3), "l"(b01));
        asm("fma.rn.f32x2 %0, %1, %2, %0;" : "+l"(acc[3][1]) : "l"(v3), "l"(b23));
    }

    // Unpack, add biases, compute per-node L2 norm, store normalized.
    float bmv[4], bsv[4];
    #pragma unroll
    for (int c = 0; c < 4; c++) {
        bmv[c] = g_bm[to * 4 + c];
        bsv[c] = g_bs[to * 4 + c];
    }

    float vals[4][4];
    #pragma unroll
    for (int r = 0; r < 4; r++) {
        float dg = degS[tn * 4 + r];
        float lo0, hi0, lo1, hi1;
        asm("mov.b64 {%0,%1}, %2;" : "=f"(lo0), "=f"(hi0) : "l"(acc[r][0]));
        asm("mov.b64 {%0,%1}, %2;" : "=f"(lo1), "=f"(hi1) : "l"(acc[r][1]));
        vals[r][0] = lo0 + dg * bmv[0] + bsv[0];
        vals[r][1] = hi0 + dg * bmv[1] + bsv[1];
        vals[r][2] = lo1 + dg * bmv[2] + bsv[2];
        vals[r][3] = hi1 + dg * bmv[3] + bsv[3];
        float ss = 0.f;
        #pragma unroll
        for (int c = 0; c < 4; c++) ss = fmaf(vals[r][c], vals[r][c], ss);
        red[(tn * 4 + r) * 17 + to] = ss;
    }
    __syncthreads();

    if (tid < 64) {
        float s = 0.f;
        #pragma unroll
        for (int t2 = 0; t2 < 16; t2++) s += red[tid * 17 + t2];
        float nrm = sqrtf(s);
        nf[tid] = 1.f / fmaxf(nrm, 1e-12f);
    }
    __syncthreads();

    #pragma unroll
    for (int r = 0; r < 4; r++) {
        int gn = n0 + tn * 4 + r;
        if (gn < NN) {
            float f = nf[tn * 4 + r];
            float4 o4 = make_float4(vals[r][0] * f, vals[r][1] * f,
                                    vals[r][2] * f, vals[r][3] * f);
            *(float4*)&out[(size_t)gn * D + to * 4] = o4;
        }
    }
}

#define SMEM_BYTES ((64 * IN2_STRIDE + 128 * D + 64 * 17 + 64 + 64) * (int)sizeof(float))

extern "C" void kernel_launch(void* const* d_in, const int* in_sizes, int n_in,
                              void* d_out, int out_size) {
    const float* x   = (const float*)d_in[0];
    const int*   ei  = (const int*)d_in[1];
    const float* bmw = (const float*)d_in[2];
    const float* bmb = (const float*)d_in[3];
    const float* bsw = (const float*)d_in[4];
    const float* bsb = (const float*)d_in[5];
    const float* lc  = (const float*)d_in[6];
    float* out = (float*)d_out;

    unsigned total = (unsigned)NE * 16u;
    unsigned nblk = 1u + (total + 255u) / 256u;
    k_scatter<<<nblk, 256>>>((const float4*)x, ei, bmw, bmb, bsw, bsb, lc);

    cudaFuncSetAttribute(k_transform, cudaFuncAttributeMaxDynamicSharedMemorySize, SMEM_BYTES);
    k_transform<<<(NN + 63) / 64, 256, SMEM_BYTES>>>(x, out);
}

// round 3
// speedup vs baseline: 1.0679x; 1.0679x over previous
#include <cuda_runtime.h>

#define NN 100000
#define NE 1250000
#define D  64
#define NB 16

// Scratch (no allocs allowed). Invariant: g_h and g_deg are ZERO at entry of
// every kernel_launch call — zero at module load, and k_transform restores
// them to zero after consuming them. No memsets needed.
__device__ float g_h[(size_t)NN * D];   // sum of x[src] per dst node
__device__ float g_deg[NN];             // in-degree (float)
__device__ float g_Wm[D * D];           // reconstructed W_msg  [i][o]
__device__ float g_Ws[D * D];           // reconstructed W_self [i][o]
__device__ float g_bm[D];
__device__ float g_bs[D];

// ---------------------------------------------------------------------------
// Kernel 1: scatter-add raw x rows (16 threads/edge, float4 vector atomics).
// Block 0 instead reconstructs weights from bases (hides under the scatter).
// ---------------------------------------------------------------------------
__global__ void k_scatter(const float4* __restrict__ x4, const int* __restrict__ ei,
                          const float* __restrict__ bmw, const float* __restrict__ bmb,
                          const float* __restrict__ bsw, const float* __restrict__ bsb,
                          const float* __restrict__ lc) {
    if (blockIdx.x == 0) {
        __shared__ float c[NB];
        if (threadIdx.x < NB) c[threadIdx.x] = lc[threadIdx.x];
        __syncthreads();
        for (int idx = threadIdx.x; idx < D * D; idx += 256) {
            float wm = 0.f, ws = 0.f;
            #pragma unroll
            for (int b = 0; b < NB; b++) {
                wm = fmaf(bmw[idx * NB + b], c[b], wm);
                ws = fmaf(bsw[idx * NB + b], c[b], ws);
            }
            g_Wm[idx] = wm;
            g_Ws[idx] = ws;
        }
        if (threadIdx.x < D) {
            int o = threadIdx.x;
            float bm = 0.f, bs = 0.f;
            #pragma unroll
            for (int b = 0; b < NB; b++) {
                bm = fmaf(bmb[o * NB + b], c[b], bm);
                bs = fmaf(bsb[o * NB + b], c[b], bs);
            }
            g_bm[o] = bm;
            g_bs[o] = bs;
        }
        return;
    }
    unsigned t = (blockIdx.x - 1) * blockDim.x + threadIdx.x;
    unsigned e = t >> 4;
    if (e >= NE) return;
    int j = t & 15;
    int src = __ldg(ei + e);
    int dst = __ldg(ei + NE + e);
    float4 v = __ldg(x4 + (size_t)src * (D / 4) + j);
    float* p = g_h + (size_t)dst * D + j * 4;
    asm volatile("red.global.add.v4.f32 [%0], {%1,%2,%3,%4};"
                 :: "l"(p), "f"(v.x), "f"(v.y), "f"(v.z), "f"(v.w)
                 : "memory");
    if (j == 0) atomicAdd(&g_deg[dst], 1.0f);
}

// ---------------------------------------------------------------------------
// Kernel 2: out = normalize( h @ Wm + x @ Ws + deg*bm + bs )
// 64 nodes x 64 cols per block, scalar FFMA 4x4 micro-tile (proven R1 path).
// Also restores g_h/g_deg to zero for the next launch.
// ---------------------------------------------------------------------------
#define IN_STRIDE 132   // 128 + 4 pad

__global__ void k_transform(const float* __restrict__ x, float* __restrict__ out) {
    extern __shared__ float smem[];
    float* In   = smem;                    // [64][IN_STRIDE]
    float* Wsh  = In + 64 * IN_STRIDE;     // [128][64] flat
    float* red  = Wsh + 128 * D;           // [64][17]
    float* nf   = red + 64 * 17;           // [64]
    float* degS = nf + 64;                 // [64]

    int tid = threadIdx.x;
    int n0  = blockIdx.x * 64;

    // Load W (rows 0..63 = Wm, 64..127 = Ws)
    {
        const float4* wm4 = (const float4*)g_Wm;
        const float4* ws4 = (const float4*)g_Ws;
        float4* w4 = (float4*)Wsh;
        #pragma unroll
        for (int i = tid; i < (D * D) / 4; i += 256) {
            w4[i] = wm4[i];
            w4[i + (D * D) / 4] = ws4[i];
        }
    }
    // Load input tile: In[n][0:64] = h row, In[n][64:128] = x row.
    // Restore g_h to zero as we go.
    {
        const float4* h4 = (const float4*)g_h;
        const float4* x4 = (const float4*)x;
        float4* h4w = (float4*)g_h;
        for (int i = tid; i < 64 * (D / 4); i += 256) {
            int n = i >> 4, j = i & 15;
            int gn = n0 + n;
            float4 hv = make_float4(0.f, 0.f, 0.f, 0.f);
            float4 xv = hv;
            if (gn < NN) {
                size_t off = (size_t)gn * (D / 4) + j;
                hv = h4[off];
                xv = x4[off];
                h4w[off] = make_float4(0.f, 0.f, 0.f, 0.f);
            }
            *(float4*)&In[n * IN_STRIDE + j * 4]      = hv;
            *(float4*)&In[n * IN_STRIDE + 64 + j * 4] = xv;
        }
    }
    // Load degree (and restore to zero)
    if (tid < 64) {
        int gn = n0 + tid;
        float dg = 0.f;
        if (gn < NN) {
            dg = g_deg[gn];
            g_deg[gn] = 0.f;
        }
        degS[tid] = dg;
    }
    __syncthreads();

    int to = tid & 15;   // col group: cols to*4 .. to*4+3
    int tn = tid >> 4;   // node group: nodes tn*4 .. tn*4+3

    float acc[4][4];
    #pragma unroll
    for (int r = 0; r < 4; r++)
        #pragma unroll
        for (int c = 0; c < 4; c++) acc[r][c] = 0.f;

    const float* a0 = &In[(tn * 4 + 0) * IN_STRIDE];
    const float* a1 = &In[(tn * 4 + 1) * IN_STRIDE];
    const float* a2 = &In[(tn * 4 + 2) * IN_STRIDE];
    const float* a3 = &In[(tn * 4 + 3) * IN_STRIDE];

    #pragma unroll 8
    for (int k = 0; k < 128; k++) {
        float4 b = *(const float4*)&Wsh[k * D + to * 4];
        float v0 = a0[k], v1 = a1[k], v2 = a2[k], v3 = a3[k];
        acc[0][0] = fmaf(v0, b.x, acc[0][0]); acc[0][1] = fmaf(v0, b.y, acc[0][1]);
        acc[0][2] = fmaf(v0, b.z, acc[0][2]); acc[0][3] = fmaf(v0, b.w, acc[0][3]);
        acc[1][0] = fmaf(v1, b.x, acc[1][0]); acc[1][1] = fmaf(v1, b.y, acc[1][1]);
        acc[1][2] = fmaf(v1, b.z, acc[1][2]); acc[1][3] = fmaf(v1, b.w, acc[1][3]);
        acc[2][0] = fmaf(v2, b.x, acc[2][0]); acc[2][1] = fmaf(v2, b.y, acc[2][1]);
        acc[2][2] = fmaf(v2, b.z, acc[2][2]); acc[2][3] = fmaf(v2, b.w, acc[2][3]);
        acc[3][0] = fmaf(v3, b.x, acc[3][0]); acc[3][1] = fmaf(v3, b.y, acc[3][1]);
        acc[3][2] = fmaf(v3, b.z, acc[3][2]); acc[3][3] = fmaf(v3, b.w, acc[3][3]);
    }

    // Epilogue: bias + deg*b_msg, per-node L2 norm, normalized store.
    float bmv[4], bsv[4];
    #pragma unroll
    for (int c = 0; c < 4; c++) {
        bmv[c] = g_bm[to * 4 + c];
        bsv[c] = g_bs[to * 4 + c];
    }

    float vals[4][4];
    #pragma unroll
    for (int r = 0; r < 4; r++) {
        float dg = degS[tn * 4 + r];
        float ss = 0.f;
        #pragma unroll
        for (int c = 0; c < 4; c++) {
            float v = acc[r][c] + dg * bmv[c] + bsv[c];
            vals[r][c] = v;
            ss = fmaf(v, v, ss);
        }
        red[(tn * 4 + r) * 17 + to] = ss;
    }
    __syncthreads();

    if (tid < 64) {
        float s = 0.f;
        #pragma unroll
        for (int t2 = 0; t2 < 16; t2++) s += red[tid * 17 + t2];
        float nrm = sqrtf(s);
        nf[tid] = 1.f / fmaxf(nrm, 1e-12f);
    }
    __syncthreads();

    #pragma unroll
    for (int r = 0; r < 4; r++) {
        int gn = n0 + tn * 4 + r;
        if (gn < NN) {
            float f = nf[tn * 4 + r];
            float4 o4 = make_float4(vals[r][0] * f, vals[r][1] * f,
                                    vals[r][2] * f, vals[r][3] * f);
            *(float4*)&out[(size_t)gn * D + to * 4] = o4;
        }
    }
}

#define SMEM_BYTES ((64 * IN_STRIDE + 128 * D + 64 * 17 + 64 + 64) * (int)sizeof(float))

extern "C" void kernel_launch(void* const* d_in, const int* in_sizes, int n_in,
                              void* d_out, int out_size) {
    const float* x   = (const float*)d_in[0];
    const int*   ei  = (const int*)d_in[1];
    const float* bmw = (const float*)d_in[2];
    const float* bmb = (const float*)d_in[3];
    const float* bsw = (const float*)d_in[4];
    const float* bsb = (const float*)d_in[5];
    const float* lc  = (const float*)d_in[6];
    float* out = (float*)d_out;

    unsigned total = (unsigned)NE * 16u;
    unsigned nblk = 1u + (total + 255u) / 256u;
    k_scatter<<<nblk, 256>>>((const float4*)x, ei, bmw, bmb, bsw, bsb, lc);

    cudaFuncSetAttribute(k_transform, cudaFuncAttributeMaxDynamicSharedMemorySize, SMEM_BYTES);
    k_transform<<<(NN + 63) / 64, 256, SMEM_BYTES>>>(x, out);
}